// round 14
// baseline (speedup 1.0000x reference)
#include <cuda_runtime.h>
#include <cuda_bf16.h>
#include <math.h>
#include <stdint.h>

#define NB 64
#define NS 256
#define NU 1024
#define NT 512
#define NTH 512
#define NBS (NB * NS)

__device__ __nv_bfloat16 g_h_h[NBS * NU], g_h_l[NBS * NU];
__device__ __nv_bfloat16 g_hpt[NBS * NU];                     // [u][b*256+s]
__device__ __nv_bfloat16 g_Wt1q_h[2048 * NU], g_Wt1q_l[2048 * NU];
__device__ __nv_bfloat16 g_Wy2t_h[NT * NU],   g_Wy2t_l[NT * NU];
__device__ __nv_bfloat16 g_Wgt_h[4096 * 1536], g_Wgt_l[4096 * 1536];
__device__ __nv_bfloat16 g_We1t_h[NU * NU],   g_We1t_l[NU * NU];
__device__ __nv_bfloat16 g_Wct_h[4096 * NU],  g_Wct_l[4096 * NU]; // Wcomb^T [m][k']
__device__ __nv_bfloat16 g_t1_h[NB * NU], g_t1_l[NB * NU];
__device__ __nv_bfloat16 g_s_h[NB * NU],  g_s_l[NB * NU];
__device__ float g_y32[NB * NT];
__device__ float g_q[NB * NU];
__device__ float g_e[NB * NS];
__device__ float g_gt[NB * 4096];
__device__ float g_bgp[4096];                                  // fused gate bias
__device__ float2 g_lut_sig[2049], g_lut_tanh[2049];
__device__ unsigned g_cnt, g_phs, g_cg[8];

#define O_LS 0
#define O_LT 16392
#define O_WK 32784
#define O_AH 44032
#define O_AL 52224
#define O_BH 60416
#define O_BL 68608
#define PSMEM 76800

#define SWZ(x) ((x) ^ (((x) >> 3) & 0x70))

__device__ __forceinline__ uint32_t smem_u32(const void* p) {
    uint32_t a;
    asm("{ .reg .u64 t; cvta.to.shared.u64 t, %1; cvt.u32.u64 %0, t; }" : "=r"(a) : "l"(p));
    return a;
}
__device__ __forceinline__ void ldsm4(uint32_t* r, uint32_t addr) {
    asm volatile("ldmatrix.sync.aligned.m8n8.x4.shared.b16 {%0,%1,%2,%3}, [%4];"
        : "=r"(r[0]), "=r"(r[1]), "=r"(r[2]), "=r"(r[3]) : "r"(addr));
}
__device__ __forceinline__ void hmma(float* d, const uint32_t* a, uint32_t b0, uint32_t b1) {
    asm volatile("mma.sync.aligned.m16n8k16.row.col.f32.bf16.bf16.f32 "
        "{%0,%1,%2,%3}, {%4,%5,%6,%7}, {%8,%9}, {%0,%1,%2,%3};"
        : "+f"(d[0]), "+f"(d[1]), "+f"(d[2]), "+f"(d[3])
        : "r"(a[0]), "r"(a[1]), "r"(a[2]), "r"(a[3]), "r"(b0), "r"(b1));
}
__device__ __forceinline__ float lut_eval(const float2* __restrict__ lut, float x) {
    float xc = fminf(fmaxf(x, -8.0f), 8.0f);
    float f  = fmaf(xc, 128.0f, 1024.0f);
    float m  = (f - 0.5f) + 12582912.0f;
    int  idx = __float_as_int(m) - 0x4B400000;
    float2 p = lut[idx];
    return fmaf(f - (m - 12582912.0f), p.y, p.x);
}
__device__ __forceinline__ void hilo(float v, __nv_bfloat16* hp, __nv_bfloat16* lp) {
    __nv_bfloat16 h = __float2bfloat16(v);
    *hp = h;
    *lp = __float2bfloat16(v - __bfloat162float(h));
}
__device__ __forceinline__ uint4 pack8(const float* v, bool hi) {
    uint16_t r[8];
#pragma unroll
    for (int j = 0; j < 8; j++) {
        __nv_bfloat16 hh = __float2bfloat16(v[j]);
        __nv_bfloat16 e  = hi ? hh : __float2bfloat16(v[j] - __bfloat162float(hh));
        r[j] = *(uint16_t*)&e;
    }
    return *(uint4*)r;
}
// two-level grid barrier: 32-CTA group counters, then master
__device__ __forceinline__ void gsync(unsigned& tgt) {
    tgt++;
    __syncthreads();
    if (threadIdx.x == 0) {
        __threadfence();
        int g = blockIdx.x >> 5;
        int gsz = min(32, (int)gridDim.x - (g << 5));
        unsigned ng = (gridDim.x + 31) >> 5;
        if (atomicAdd(&g_cg[g], 1u) == (unsigned)(gsz - 1)) {
            g_cg[g] = 0;                       // safe: re-arrival blocked until flip
            if (atomicAdd(&g_cnt, 1u) == ng - 1) {
                g_cnt = 0;
                __threadfence();
                atomicExch(&g_phs, tgt);
            }
        }
        while (*(volatile unsigned*)&g_phs < tgt) { }
    }
    __syncthreads();
}

__global__ void k_init() {
    int tid = threadIdx.x;
    if (tid == 0) { g_cnt = 0; g_phs = 0; }
    if (tid < 8) g_cg[tid] = 0;
    for (int i = tid; i < 2049; i += NTH) {
        float x0 = -8.0f + i * (1.0f / 128.0f), x1 = x0 + (1.0f / 128.0f);
        float sa = 1.0f / (1.0f + expf(-x0));
        float sb = (i == 2048) ? sa : 1.0f / (1.0f + expf(-x1));
        g_lut_sig[i] = make_float2(sa, sb - sa);
        float ta = tanhf(x0), tb = (i == 2048) ? ta : tanhf(x1);
        g_lut_tanh[i] = make_float2(ta, tb - ta);
    }
}

// D[64 x 64] = A[m0..+64][K](hi/lo) @ B[64][K](hi/lo)^T, 3-term hi/lo bf16 HMMA.
__device__ __forceinline__ void mma_job(
    char* dyn, uint32_t su,
    const __nv_bfloat16* aH, const __nv_bfloat16* aL, int lda,
    const __nv_bfloat16* bH, const __nv_bfloat16* bL, int ldb,
    int nch, float acc[2][4])
{
    const int tid = threadIdx.x, lane = tid & 31, warp = tid >> 5;
    const int wm = warp >> 2, wn = warp & 3;
    const int sr = tid >> 3, ss = tid & 7;
    const int arow = wm * 16 + (lane & 15), ablk = lane >> 4;
    const int brow = wn * 16 + (lane & 7) + ((lane >> 4) << 3), bblk = (lane >> 3) & 1;
    const uint32_t soff = SWZ((uint32_t)(sr * 128 + ss * 16));

    uint4 vah = *(const uint4*)(aH + (size_t)sr * lda + ss * 8);
    uint4 val = *(const uint4*)(aL + (size_t)sr * lda + ss * 8);
    uint4 vbh = __ldcg((const uint4*)(bH + (size_t)sr * ldb + ss * 8));
    uint4 vbl = __ldcg((const uint4*)(bL + (size_t)sr * ldb + ss * 8));

    for (int c = 0; c < nch; c++) {
        __syncthreads();
        *(uint4*)(dyn + O_AH + soff) = vah;
        *(uint4*)(dyn + O_AL + soff) = val;
        *(uint4*)(dyn + O_BH + soff) = vbh;
        *(uint4*)(dyn + O_BL + soff) = vbl;
        __syncthreads();
        if (c + 1 < nch) {
            int k = (c + 1) * 64 + ss * 8;
            vah = *(const uint4*)(aH + (size_t)sr * lda + k);
            val = *(const uint4*)(aL + (size_t)sr * lda + k);
            vbh = __ldcg((const uint4*)(bH + (size_t)sr * ldb + k));
            vbl = __ldcg((const uint4*)(bL + (size_t)sr * ldb + k));
        }
#pragma unroll
        for (int ks = 0; ks < 4; ks++) {
            uint32_t ao = SWZ((uint32_t)(arow * 128 + ks * 32 + ablk * 16));
            uint32_t bo = SWZ((uint32_t)(brow * 128 + ks * 32 + bblk * 16));
            uint32_t ah[4], al[4], bh[4], bl[4];
            ldsm4(ah, su + O_AH + ao);
            ldsm4(al, su + O_AL + ao);
            ldsm4(bh, su + O_BH + bo);
            ldsm4(bl, su + O_BL + bo);
            hmma(acc[0], ah, bh[0], bh[1]);
            hmma(acc[1], ah, bh[2], bh[3]);
            hmma(acc[0], ah, bl[0], bl[1]);
            hmma(acc[1], ah, bl[2], bl[3]);
            hmma(acc[0], al, bh[0], bh[1]);
            hmma(acc[1], al, bh[2], bh[3]);
        }
    }
}

// B source fp32, converted hi/lo on the fly (used only for the Wcomb build).
__device__ __forceinline__ void mma_job_f32b(
    char* dyn, uint32_t su,
    const __nv_bfloat16* aH, const __nv_bfloat16* aL, int lda,
    const float* bF, int ldb, int nch, float acc[2][4])
{
    const int tid = threadIdx.x, lane = tid & 31, warp = tid >> 5;
    const int wm = warp >> 2, wn = warp & 3;
    const int sr = tid >> 3, ss = tid & 7;
    const int arow = wm * 16 + (lane & 15), ablk = lane >> 4;
    const int brow = wn * 16 + (lane & 7) + ((lane >> 4) << 3), bblk = (lane >> 3) & 1;
    const uint32_t soff = SWZ((uint32_t)(sr * 128 + ss * 16));

    uint4 vah = *(const uint4*)(aH + (size_t)sr * lda + ss * 8);
    uint4 val = *(const uint4*)(aL + (size_t)sr * lda + ss * 8);
    float fb[8];
    {
        float4 f0 = __ldcg((const float4*)(bF + (size_t)sr * ldb + ss * 8));
        float4 f1 = __ldcg((const float4*)(bF + (size_t)sr * ldb + ss * 8 + 4));
        fb[0] = f0.x; fb[1] = f0.y; fb[2] = f0.z; fb[3] = f0.w;
        fb[4] = f1.x; fb[5] = f1.y; fb[6] = f1.z; fb[7] = f1.w;
    }
    for (int c = 0; c < nch; c++) {
        uint4 vbh = pack8(fb, true);
        uint4 vbl = pack8(fb, false);
        __syncthreads();
        *(uint4*)(dyn + O_AH + soff) = vah;
        *(uint4*)(dyn + O_AL + soff) = val;
        *(uint4*)(dyn + O_BH + soff) = vbh;
        *(uint4*)(dyn + O_BL + soff) = vbl;
        __syncthreads();
        if (c + 1 < nch) {
            int k = (c + 1) * 64 + ss * 8;
            vah = *(const uint4*)(aH + (size_t)sr * lda + k);
            val = *(const uint4*)(aL + (size_t)sr * lda + k);
            float4 f0 = __ldcg((const float4*)(bF + (size_t)sr * ldb + k));
            float4 f1 = __ldcg((const float4*)(bF + (size_t)sr * ldb + k + 4));
            fb[0] = f0.x; fb[1] = f0.y; fb[2] = f0.z; fb[3] = f0.w;
            fb[4] = f1.x; fb[5] = f1.y; fb[6] = f1.z; fb[7] = f1.w;
        }
#pragma unroll
        for (int ks = 0; ks < 4; ks++) {
            uint32_t ao = SWZ((uint32_t)(arow * 128 + ks * 32 + ablk * 16));
            uint32_t bo = SWZ((uint32_t)(brow * 128 + ks * 32 + bblk * 16));
            uint32_t ah[4], al[4], bh[4], bl[4];
            ldsm4(ah, su + O_AH + ao);
            ldsm4(al, su + O_AL + ao);
            ldsm4(bh, su + O_BH + bo);
            ldsm4(bl, su + O_BL + bo);
            hmma(acc[0], ah, bh[0], bh[1]);
            hmma(acc[1], ah, bh[2], bh[3]);
            hmma(acc[0], ah, bl[0], bl[1]);
            hmma(acc[1], ah, bl[2], bl[3]);
            hmma(acc[0], al, bh[0], bh[1]);
            hmma(acc[1], al, bh[2], bh[3]);
        }
    }
}
#define EPI_LOOP(body) do {                                                     \
    const int _wm = (threadIdx.x >> 7), _wn = (threadIdx.x >> 5) & 3;           \
    const int _tq = (threadIdx.x & 31) >> 2, _tr = threadIdx.x & 3;             \
    _Pragma("unroll") for (int _i = 0; _i < 2; _i++) {                          \
        int ml = _wm * 16 + _tq + _i * 8;                                       \
        _Pragma("unroll") for (int _na = 0; _na < 2; _na++)                     \
        _Pragma("unroll") for (int _j = 0; _j < 2; _j++) {                      \
            int nl = _wn * 16 + _na * 8 + _tr * 2 + _j;                         \
            float v = acc[_na][_i * 2 + _j];                                    \
            body                                                                 \
        }                                                                        \
    }                                                                            \
} while (0)

__global__ __launch_bounds__(NTH, 1) void k_all(
    const float* __restrict__ h,  const float* __restrict__ s0,
    const float* __restrict__ Wy1, const float* __restrict__ by1,
    const float* __restrict__ Wy2, const float* __restrict__ by2,
    const float* __restrict__ We1, const float* __restrict__ be1,
    const float* __restrict__ We2, const float* __restrict__ be2,
    const float* __restrict__ Wi,  const float* __restrict__ bi,
    const float* __restrict__ Wf,  const float* __restrict__ bf,
    const float* __restrict__ Wg,  const float* __restrict__ bg,
    const float* __restrict__ Wo,  const float* __restrict__ bo,
    float* __restrict__ out)
{
    extern __shared__ char dyn[];
    float2* lsig  = (float2*)(dyn + O_LS);
    float2* ltanh = (float2*)(dyn + O_LT);
    float*  work  = (float*)(dyn + O_WK);
    const uint32_t su = smem_u32(dyn);
    const int tid = threadIdx.x, bid = blockIdx.x;
    const int gth = gridDim.x * NTH, gid = bid * NTH + tid;
    unsigned tgt = 0;

    for (int i = tid; i < 2049; i += NTH) { lsig[i] = g_lut_sig[i]; ltanh[i] = g_lut_tanh[i]; }
    __syncthreads();
    const float be2v = be2[0];

    // ---- A1: conversions + weight transposes (hi/lo) + state init ----
    for (size_t i = gid; i < (size_t)NBS * NU; i += gth)
        hilo(__ldcs(h + i), g_h_h + i, g_h_l + i);
    for (int i = gid; i < 2048 * NU; i += gth) {
        int k = i >> 11, m = i & 2047;
        float v = (m < NU) ? Wy1[(size_t)k * NU + m] : We1[(size_t)(NU + k) * NU + (m - NU)];
        hilo(v, g_Wt1q_h + (size_t)m * NU + k, g_Wt1q_l + (size_t)m * NU + k);
    }
    for (int i = gid; i < NT * NU; i += gth) {
        int k = i >> 9, m = i & 511;
        hilo(Wy2[(size_t)k * NT + m], g_Wy2t_h + (size_t)m * NU + k, g_Wy2t_l + (size_t)m * NU + k);
    }
    for (int i = gid; i < 4096 * 1536; i += gth) {
        int k = i >> 12, m = i & 4095, gate = m >> 10, u = m & 1023;
        const float* W = (gate == 0) ? Wi : (gate == 1) ? Wf : (gate == 2) ? Wg : Wo;
        hilo(W[(size_t)k * NU + u], g_Wgt_h + (size_t)m * 1536 + k, g_Wgt_l + (size_t)m * 1536 + k);
    }
    for (int i = gid; i < NU * NU; i += gth) {
        int k = i >> 10, m = i & 1023;
        hilo(We1[(size_t)k * NU + m], g_We1t_h + (size_t)m * NU + k, g_We1t_l + (size_t)m * NU + k);
    }
    for (int i = gid; i < NB * NU; i += gth)
        hilo(s0[i], g_s_h + i, g_s_l + i);
    for (int i = gid; i < NB * NT; i += gth)
        g_y32[i] = by2[i & 511];
    for (int i = gid; i < NB * NS; i += gth)
        g_e[i] = 0.f;
    gsync(tgt);

    // ---- A2: hproj (4096 jobs) + A3: Wcomb (1024 jobs) + bgp (16 jobs) ----
    for (int j = bid; j < 5136; j += gridDim.x) {
        if (j < 4096) {
            int m0 = (j >> 8) * 64, n0 = (j & 255) * 64;
            float acc[2][4] = {};
            mma_job(dyn, su, g_We1t_h + (size_t)m0 * NU, g_We1t_l + (size_t)m0 * NU, NU,
                    g_h_h + (size_t)n0 * NU, g_h_l + (size_t)n0 * NU, NU, 16, acc);
            EPI_LOOP({
                g_hpt[(size_t)(m0 + ml) * NBS + n0 + nl] = __float2bfloat16(v);
            });
        } else if (j < 5120) {
            // Wcomb[k'][m] = sum_j Wg[j][m] * Wy2[k'][j]  -> store transposed [m][k']
            int jw = j - 4096, m0 = (jw >> 4) * 64, k0 = (jw & 15) * 64;
            float acc[2][4] = {};
            mma_job_f32b(dyn, su, g_Wgt_h + (size_t)m0 * 1536,
                         g_Wgt_l + (size_t)m0 * 1536, 1536,
                         Wy2 + (size_t)k0 * NT, NT, 8, acc);
            EPI_LOOP({
                hilo(v, g_Wct_h + (size_t)(m0 + ml) * NU + k0 + nl,
                        g_Wct_l + (size_t)(m0 + ml) * NU + k0 + nl);
            });
        } else if (tid < 256) {
            // bgp[m] = gate_bias[m] + sum_j by2[j] * Wg[j][m]
            int m = (j - 5120) * 256 + tid;
            int gate = m >> 10, u = m & 1023;
            float s = (gate == 0) ? bi[u] : (gate == 1) ? bf[u] : (gate == 2) ? bg[u] : bo[u];
            for (int jj = 0; jj < NT; jj++) {
                float w = __bfloat162float(g_Wgt_h[(size_t)m * 1536 + jj]) +
                          __bfloat162float(g_Wgt_l[(size_t)m * 1536 + jj]);
                s = fmaf(by2[jj], w, s);
            }
            g_bgp[m] = s;
        }
    }
    gsync(tgt);

    // ================= scan: 3 barriers/step =================
    for (int t = 0; t < NS; t++) {
        // SP1: t1|q (bids 0-31, K=1024) + gates-s -> g_gt store (bids 32-95)
        if (bid < 32) {
            int m0 = bid * 64;
            float acc[2][4] = {};
            mma_job(dyn, su, g_Wt1q_h + (size_t)m0 * NU, g_Wt1q_l + (size_t)m0 * NU, NU,
                    g_s_h, g_s_l, NU, 16, acc);
            EPI_LOOP({
                int m = m0 + ml;
                if (m < NU) {
                    float tv = lut_eval(ltanh, v + by1[m]);
                    hilo(tv, g_t1_h + nl * NU + m, g_t1_l + nl * NU + m);
                } else {
                    g_q[nl * NU + (m - NU)] = v + be1[m - NU];
                }
            });
        } else if (bid < 96) {
            int m0 = (bid - 32) * 64;
            float acc[2][4] = {};
            mma_job(dyn, su, g_Wgt_h + (size_t)m0 * 1536 + 512,
                    g_Wgt_l + (size_t)m0 * 1536 + 512, 1536,
                    g_s_h, g_s_l, NU, 16, acc);
            EPI_LOOP({
                g_gt[nl * 4096 + m0 + ml] = v;
            });
        }
        gsync(tgt);

        // SP2 (272 jobs, strided): y split-K (16) + energy (128) + tcomb halves (128)
        for (int j = bid; j < 272; j += gridDim.x) {
            if (j < 16) {
                int m0 = (j >> 1) * 64, kh = j & 1;
                float acc[2][4] = {};
                mma_job(dyn, su, g_Wy2t_h + (size_t)m0 * NU + kh * 512,
                        g_Wy2t_l + (size_t)m0 * NU + kh * 512, NU,
                        g_t1_h + kh * 512, g_t1_l + kh * 512, NU, 8, acc);
                EPI_LOOP({
                    atomicAdd(&g_y32[nl * NT + m0 + ml], v);
                });
            } else if (j < 144) {
                int e = j - 16, b = e >> 1, uh = e & 1;
                float2* swq = (float2*)work;
                {
                    int u = uh * 512 + tid;
                    swq[tid] = make_float2(__ldcg(g_q + b * NU + u), We2[u]);
                }
                __syncthreads();
                int s = tid & 255, up = tid >> 8;
                const unsigned short* hp = (const unsigned short*)g_hpt +
                                           (size_t)(uh * 512 + up * 256) * NBS + b * NS + s;
                float av = 0.f;
#pragma unroll 8
                for (int u = 0; u < 256; u++) {
                    unsigned short raw = __ldcg(hp + (size_t)u * NBS);
                    float hv = __int_as_float((int)((unsigned)raw << 16));
                    float2 qw = swq[up * 256 + u];
                    av = fmaf(lut_eval(lsig, hv + qw.x), qw.y, av);
                }
                float* ew = work + 1024;
                ew[tid] = av;
                __syncthreads();
                if (tid < 256) atomicAdd(&g_e[b * NS + tid], ew[tid] + ew[tid + 256]);
                __syncthreads();
            } else {
                // tcomb: gates += t1 @ Wcomb (split-K x2)
                int jt = j - 144, m0 = (jt >> 1) * 64, kh = jt & 1;
                float acc[2][4] = {};
                mma_job(dyn, su, g_Wct_h + (size_t)m0 * NU + kh * 512,
                        g_Wct_l + (size_t)m0 * NU + kh * 512, NU,
                        g_t1_h + kh * 512, g_t1_l + kh * 512, NU, 8, acc);
                EPI_LOOP({
                    atomicAdd(&g_gt[nl * 4096 + m0 + ml], v);
                });
            }
        }
        gsync(tgt);

        // SP3: fused softmax+context+s' (bids 0-63) ; housekeeping (bids 64-151)
        if (bid < NB) {
            int b = bid;
            float ev = (tid < NS) ? lut_eval(lsig, __ldcg(g_e + b * NS + tid) + be2v) : -1e30f;
            work[tid] = ev;
            __syncthreads();
            for (int o = 256; o > 0; o >>= 1) {
                if (tid < o) work[tid] = fmaxf(work[tid], work[tid + o]);
                __syncthreads();
            }
            float mx = work[0];
            __syncthreads();
            float p = expf(ev - mx);
            work[tid] = p;
            __syncthreads();
            for (int o = 256; o > 0; o >>= 1) {
                if (tid < o) work[tid] += work[tid + o];
                __syncthreads();
            }
            float rinv = 1.0f / work[0];
            float* aw = work + 512;
            if (tid < NS) aw[tid] = p * rinv;
            __syncthreads();
            const unsigned* hb = (const unsigned*)(g_h_h + (size_t)b * NS * NU) + tid;
            float a0 = 0.f, a1 = 0.f, a2 = 0.f, a3 = 0.f;
#pragma unroll 4
            for (int s2 = 0; s2 < NS; s2 += 2) {
                unsigned r0 = __ldcg(hb + (size_t)(s2 + 0) * (NU / 2));
                unsigned r1 = __ldcg(hb + (size_t)(s2 + 1) * (NU / 2));
                float w0 = aw[s2], w1 = aw[s2 + 1];
                a0 = fmaf(__int_as_float((int)(r0 << 16)), w0, a0);
                a1 = fmaf(__int_as_float((int)(r0 & 0xFFFF0000u)), w0, a1);
                a2 = fmaf(__int_as_float((int)(r1 << 16)), w1, a2);
                a3 = fmaf(__int_as_float((int)(r1 & 0xFFFF0000u)), w1, a3);
            }
            float c0 = a0 + a2, c1 = a1 + a3;
            // fused s' for u = 2tid, 2tid+1 (gates complete since SP2)
            const float* gp = g_gt + b * 4096;
            int u0 = 2 * tid;
#pragma unroll
            for (int uu = 0; uu < 2; uu++) {
                int u = u0 + uu;
                float cv = (uu == 0) ? c0 : c1;
                float iv = lut_eval(lsig,  __ldcg(gp + u)        + g_bgp[u]);
                float fv = lut_eval(lsig,  __ldcg(gp + 1024 + u) + g_bgp[1024 + u]);
                float gv = lut_eval(ltanh, __ldcg(gp + 2048 + u) + g_bgp[2048 + u]);
                float ov = lut_eval(lsig,  __ldcg(gp + 3072 + u) + g_bgp[3072 + u]);
                float sv = ov * lut_eval(ltanh, fmaf(fv, cv, iv * gv));
                hilo(sv, g_s_h + b * NU + u, g_s_l + b * NU + u);
            }
        } else {
            // y out-write + reseed; zero g_e for next step
            int hb2 = bid - NB, nh = gridDim.x - NB;
            for (int i = hb2 * NTH + tid; i < NB * NT; i += nh * NTH) {
                int n = i >> 9, m = i & 511;
                out[((size_t)n * NS + t) * NT + m] = __ldcg(g_y32 + i);
                g_y32[i] = by2[m];
            }
            for (int i = hb2 * NTH + tid; i < NB * NS; i += nh * NTH)
                g_e[i] = 0.f;
        }
        gsync(tgt);
    }
}

extern "C" void kernel_launch(void* const* d_in, const int* in_sizes, int n_in,
                              void* d_out, int out_size) {
    (void)in_sizes; (void)n_in; (void)out_size;
    const float* h   = (const float*)d_in[0];
    const float* s0  = (const float*)d_in[1];
    const float* Wy1 = (const float*)d_in[2];
    const float* by1 = (const float*)d_in[3];
    const float* Wy2 = (const float*)d_in[4];
    const float* by2 = (const float*)d_in[5];
    const float* We1 = (const float*)d_in[6];
    const float* be1 = (const float*)d_in[7];
    const float* We2 = (const float*)d_in[8];
    const float* be2 = (const float*)d_in[9];
    const float* Wf  = (const float*)d_in[10];
    const float* bf  = (const float*)d_in[11];
    const float* Wi  = (const float*)d_in[12];
    const float* bi  = (const float*)d_in[13];
    const float* Wg  = (const float*)d_in[14];
    const float* bg  = (const float*)d_in[15];
    const float* Wo  = (const float*)d_in[16];
    const float* bo  = (const float*)d_in[17];
    float* out = (float*)d_out;

    int nsm = 148;
    cudaDeviceGetAttribute(&nsm, cudaDevAttrMultiProcessorCount, 0);
    static int sset = 0;
    if (!sset) {
        cudaFuncSetAttribute(k_all, cudaFuncAttributeMaxDynamicSharedMemorySize, PSMEM);
        sset = 1;
    }
    k_init<<<1, NTH>>>();
    k_all<<<nsm, NTH, PSMEM>>>(h, s0, Wy1, by1, Wy2, by2, We1, be1, We2, be2,
                               Wi, bi, Wf, bf, Wg, bg, Wo, bo, out);
}

// round 15
// speedup vs baseline: 1.3152x; 1.3152x over previous
#include <cuda_runtime.h>
#include <cuda_fp16.h>
#include <math.h>
#include <stdint.h>

#define NB 64
#define NS 256
#define NU 1024
#define NT 512
#define NTH 512
#define NBS (NB * NS)

__device__ __half g_h_h[NBS * NU], g_h_l[NBS * NU];   // fp16 hi/lo of h
__device__ __half g_hpt[NBS * NU];                    // hproj^T [u][b*256+s], fp16
__device__ __half g_Wt1q[2048 * NU];                  // single fp16 weights
__device__ __half g_Wy2t[NT * NU];
__device__ __half g_Wgt[4096 * 1536];
__device__ __half g_We1t[NU * NU];
__device__ __half g_t1_h[NB * NU], g_t1_l[NB * NU];
__device__ __half g_s_h[NB * NU],  g_s_l[NB * NU];
__device__ float g_y32[NB * NT];
__device__ float g_q[NB * NU];
__device__ float g_e[NB * NS];
__device__ float g_gt[NB * 4096];
__device__ float2 g_lut_sig[2049], g_lut_tanh[2049];
__device__ unsigned g_cnt, g_phs;

#define O_LS 0
#define O_LT 16392
#define O_WK 32784
#define O_AH 44032
#define O_BH 52224
#define O_BL 60416
#define PSMEM 68608

#define SWZ(x) ((x) ^ (((x) >> 3) & 0x70))

__device__ __forceinline__ uint32_t smem_u32(const void* p) {
    uint32_t a;
    asm("{ .reg .u64 t; cvta.to.shared.u64 t, %1; cvt.u32.u64 %0, t; }" : "=r"(a) : "l"(p));
    return a;
}
__device__ __forceinline__ void ldsm4(uint32_t* r, uint32_t addr) {
    asm volatile("ldmatrix.sync.aligned.m8n8.x4.shared.b16 {%0,%1,%2,%3}, [%4];"
        : "=r"(r[0]), "=r"(r[1]), "=r"(r[2]), "=r"(r[3]) : "r"(addr));
}
__device__ __forceinline__ void hmma(float* d, const uint32_t* a, uint32_t b0, uint32_t b1) {
    asm volatile("mma.sync.aligned.m16n8k16.row.col.f32.f16.f16.f32 "
        "{%0,%1,%2,%3}, {%4,%5,%6,%7}, {%8,%9}, {%0,%1,%2,%3};"
        : "+f"(d[0]), "+f"(d[1]), "+f"(d[2]), "+f"(d[3])
        : "r"(a[0]), "r"(a[1]), "r"(a[2]), "r"(a[3]), "r"(b0), "r"(b1));
}
__device__ __forceinline__ float lut_eval(const float2* __restrict__ lut, float x) {
    float xc = fminf(fmaxf(x, -8.0f), 8.0f);
    float f  = fmaf(xc, 128.0f, 1024.0f);
    float m  = (f - 0.5f) + 12582912.0f;
    int  idx = __float_as_int(m) - 0x4B400000;
    float2 p = lut[idx];
    return fmaf(f - (m - 12582912.0f), p.y, p.x);
}
__device__ __forceinline__ void hilo16(float v, __half* hp, __half* lp) {
    __half h = __float2half_rn(v);
    *hp = h;
    *lp = __float2half_rn(v - __half2float(h));
}
__device__ __forceinline__ void gsync(unsigned& tgt) {
    tgt++;
    __syncthreads();
    if (threadIdx.x == 0) {
        __threadfence();
        if (atomicAdd(&g_cnt, 1u) == gridDim.x - 1) {
            g_cnt = 0; __threadfence(); atomicExch(&g_phs, tgt);
        } else {
            while (*(volatile unsigned*)&g_phs < tgt) { }
        }
    }
    __syncthreads();
}

__global__ void k_init() {
    int tid = threadIdx.x;
    if (tid == 0) { g_cnt = 0; g_phs = 0; }
    for (int i = tid; i < 2049; i += NTH) {
        float x0 = -8.0f + i * (1.0f / 128.0f), x1 = x0 + (1.0f / 128.0f);
        float sa = 1.0f / (1.0f + expf(-x0));
        float sb = (i == 2048) ? sa : 1.0f / (1.0f + expf(-x1));
        g_lut_sig[i] = make_float2(sa, sb - sa);
        float ta = tanhf(x0), tb = (i == 2048) ? ta : tanhf(x1);
        g_lut_tanh[i] = make_float2(ta, tb - ta);
    }
}

// D[64x64] = A[m0..+64][K](fp16) @ B[64][K](fp16 hi/lo)^T ; 2-term HMMA.
__device__ __forceinline__ void mma_job(
    char* dyn, uint32_t su,
    const __half* A, int lda,
    const __half* bH, const __half* bL, int ldb,
    int nch, float acc[2][4])
{
    const int tid = threadIdx.x, lane = tid & 31, warp = tid >> 5;
    const int wm = warp >> 2, wn = warp & 3;
    const int sr = tid >> 3, ss = tid & 7;
    const int arow = wm * 16 + (lane & 15), ablk = lane >> 4;
    const int brow = wn * 16 + (lane & 7) + ((lane >> 4) << 3), bblk = (lane >> 3) & 1;
    const uint32_t soff = SWZ((uint32_t)(sr * 128 + ss * 16));

    uint4 va  = *(const uint4*)(A + (size_t)sr * lda + ss * 8);
    uint4 vbh = __ldcg((const uint4*)(bH + (size_t)sr * ldb + ss * 8));
    uint4 vbl = __ldcg((const uint4*)(bL + (size_t)sr * ldb + ss * 8));

    for (int c = 0; c < nch; c++) {
        __syncthreads();
        *(uint4*)(dyn + O_AH + soff) = va;
        *(uint4*)(dyn + O_BH + soff) = vbh;
        *(uint4*)(dyn + O_BL + soff) = vbl;
        __syncthreads();
        if (c + 1 < nch) {
            int k = (c + 1) * 64 + ss * 8;
            va  = *(const uint4*)(A + (size_t)sr * lda + k);
            vbh = __ldcg((const uint4*)(bH + (size_t)sr * ldb + k));
            vbl = __ldcg((const uint4*)(bL + (size_t)sr * ldb + k));
        }
#pragma unroll
        for (int ks = 0; ks < 4; ks++) {
            uint32_t ao = SWZ((uint32_t)(arow * 128 + ks * 32 + ablk * 16));
            uint32_t bo = SWZ((uint32_t)(brow * 128 + ks * 32 + bblk * 16));
            uint32_t ah[4], bh[4], bl[4];
            ldsm4(ah, su + O_AH + ao);
            ldsm4(bh, su + O_BH + bo);
            ldsm4(bl, su + O_BL + bo);
            hmma(acc[0], ah, bh[0], bh[1]);
            hmma(acc[1], ah, bh[2], bh[3]);
            hmma(acc[0], ah, bl[0], bl[1]);
            hmma(acc[1], ah, bl[2], bl[3]);
        }
    }
}

// B source fp32, hi/lo fp16 packed on the fly (every thread stores BOTH tiles).
__device__ __forceinline__ void mma_job_f32b(
    char* dyn, uint32_t su,
    const __half* A, int lda,
    const float* bF, int ldb, int nch, float acc[2][4])
{
    const int tid = threadIdx.x, lane = tid & 31, warp = tid >> 5;
    const int wm = warp >> 2, wn = warp & 3;
    const int sr = tid >> 3, ss = tid & 7;
    const int arow = wm * 16 + (lane & 15), ablk = lane >> 4;
    const int brow = wn * 16 + (lane & 7) + ((lane >> 4) << 3), bblk = (lane >> 3) & 1;
    const uint32_t soff = SWZ((uint32_t)(sr * 128 + ss * 16));

    uint4 va = *(const uint4*)(A + (size_t)sr * lda + ss * 8);
    float fb[8];
    {
        float4 f0 = __ldcg((const float4*)(bF + (size_t)sr * ldb + ss * 8));
        float4 f1 = __ldcg((const float4*)(bF + (size_t)sr * ldb + ss * 8 + 4));
        fb[0] = f0.x; fb[1] = f0.y; fb[2] = f0.z; fb[3] = f0.w;
        fb[4] = f1.x; fb[5] = f1.y; fb[6] = f1.z; fb[7] = f1.w;
    }
    for (int c = 0; c < nch; c++) {
        uint16_t rh[8], rl[8];
#pragma unroll
        for (int j = 0; j < 8; j++) {
            __half hh = __float2half_rn(fb[j]);
            __half ll = __float2half_rn(fb[j] - __half2float(hh));
            rh[j] = *(uint16_t*)&hh;
            rl[j] = *(uint16_t*)&ll;
        }
        uint4 vbh = *(uint4*)rh, vbl = *(uint4*)rl;
        __syncthreads();
        *(uint4*)(dyn + O_AH + soff) = va;
        *(uint4*)(dyn + O_BH + soff) = vbh;
        *(uint4*)(dyn + O_BL + soff) = vbl;
        __syncthreads();
        if (c + 1 < nch) {
            int k = (c + 1) * 64 + ss * 8;
            va = *(const uint4*)(A + (size_t)sr * lda + k);
            float4 f0 = __ldcg((const float4*)(bF + (size_t)sr * ldb + k));
            float4 f1 = __ldcg((const float4*)(bF + (size_t)sr * ldb + k + 4));
            fb[0] = f0.x; fb[1] = f0.y; fb[2] = f0.z; fb[3] = f0.w;
            fb[4] = f1.x; fb[5] = f1.y; fb[6] = f1.z; fb[7] = f1.w;
        }
#pragma unroll
        for (int ks = 0; ks < 4; ks++) {
            uint32_t ao = SWZ((uint32_t)(arow * 128 + ks * 32 + ablk * 16));
            uint32_t bo = SWZ((uint32_t)(brow * 128 + ks * 32 + bblk * 16));
            uint32_t ah[4], bh[4], bl[4];
            ldsm4(ah, su + O_AH + ao);
            ldsm4(bh, su + O_BH + bo);
            ldsm4(bl, su + O_BL + bo);
            hmma(acc[0], ah, bh[0], bh[1]);
            hmma(acc[1], ah, bh[2], bh[3]);
            hmma(acc[0], ah, bl[0], bl[1]);
            hmma(acc[1], ah, bl[2], bl[3]);
        }
    }
}
#define EPI_LOOP(body) do {                                                     \
    const int _wm = (threadIdx.x >> 7), _wn = (threadIdx.x >> 5) & 3;           \
    const int _tq = (threadIdx.x & 31) >> 2, _tr = threadIdx.x & 3;             \
    _Pragma("unroll") for (int _i = 0; _i < 2; _i++) {                          \
        int ml = _wm * 16 + _tq + _i * 8;                                       \
        _Pragma("unroll") for (int _na = 0; _na < 2; _na++)                     \
        _Pragma("unroll") for (int _j = 0; _j < 2; _j++) {                      \
            int nl = _wn * 16 + _na * 8 + _tr * 2 + _j;                         \
            float v = acc[_na][_i * 2 + _j];                                    \
            body                                                                 \
        }                                                                        \
    }                                                                            \
} while (0)

__global__ __launch_bounds__(NTH, 1) void k_all(
    const float* __restrict__ h,  const float* __restrict__ s0,
    const float* __restrict__ Wy1, const float* __restrict__ by1,
    const float* __restrict__ Wy2, const float* __restrict__ by2,
    const float* __restrict__ We1, const float* __restrict__ be1,
    const float* __restrict__ We2, const float* __restrict__ be2,
    const float* __restrict__ Wi,  const float* __restrict__ bi,
    const float* __restrict__ Wf,  const float* __restrict__ bf,
    const float* __restrict__ Wg,  const float* __restrict__ bg,
    const float* __restrict__ Wo,  const float* __restrict__ bo,
    float* __restrict__ out)
{
    extern __shared__ char dyn[];
    float2* lsig  = (float2*)(dyn + O_LS);
    float2* ltanh = (float2*)(dyn + O_LT);
    float*  work  = (float*)(dyn + O_WK);
    const uint32_t su = smem_u32(dyn);
    const int tid = threadIdx.x, bid = blockIdx.x;
    const int gth = gridDim.x * NTH, gid = bid * NTH + tid;
    unsigned tgt = 0;

    for (int i = tid; i < 2049; i += NTH) { lsig[i] = g_lut_sig[i]; ltanh[i] = g_lut_tanh[i]; }
    __syncthreads();
    const float be2v = be2[0];

    // ---- A1: conversions + weight transposes ----
    for (size_t i = gid; i < (size_t)NBS * NU; i += gth)
        hilo16(__ldcs(h + i), g_h_h + i, g_h_l + i);
    for (int i = gid; i < 2048 * NU; i += gth) {
        int k = i >> 11, m = i & 2047;
        float v = (m < NU) ? Wy1[(size_t)k * NU + m] : We1[(size_t)(NU + k) * NU + (m - NU)];
        g_Wt1q[(size_t)m * NU + k] = __float2half_rn(v);
    }
    for (int i = gid; i < NT * NU; i += gth) {
        int k = i >> 9, m = i & 511;
        g_Wy2t[(size_t)m * NU + k] = __float2half_rn(Wy2[(size_t)k * NT + m]);
    }
    for (int i = gid; i < 4096 * 1536; i += gth) {
        int k = i >> 12, m = i & 4095, gate = m >> 10, u = m & 1023;
        const float* W = (gate == 0) ? Wi : (gate == 1) ? Wf : (gate == 2) ? Wg : Wo;
        g_Wgt[(size_t)m * 1536 + k] = __float2half_rn(W[(size_t)k * NU + u]);
    }
    for (int i = gid; i < NU * NU; i += gth) {
        int k = i >> 10, m = i & 1023;
        g_We1t[(size_t)m * NU + k] = __float2half_rn(We1[(size_t)k * NU + m]);
    }
    for (int i = gid; i < NB * NU; i += gth)
        hilo16(s0[i], g_s_h + i, g_s_l + i);
    for (int i = gid; i < NB * NT; i += gth)
        g_y32[i] = by2[i & 511];
    for (int i = gid; i < NB * NS; i += gth)
        g_e[i] = 0.f;
    gsync(tgt);

    // ---- A2: hproj = We1h^T @ h^T -> g_hpt[u][bs] (4096 jobs) ----
    for (int j = bid; j < 4096; j += gridDim.x) {
        int m0 = (j >> 8) * 64, n0 = (j & 255) * 64;
        float acc[2][4] = {};
        mma_job(dyn, su, g_We1t + (size_t)m0 * NU, NU,
                g_h_h + (size_t)n0 * NU, g_h_l + (size_t)n0 * NU, NU, 16, acc);
        EPI_LOOP({
            g_hpt[(size_t)(m0 + ml) * NBS + n0 + nl] = __float2half_rn(v);
        });
    }
    gsync(tgt);

    // =========================== scan (4 barriers/step) ===========================
    for (int t = 0; t < NS; t++) {
        // P1: t1q (bids 0-31) + gates-s partial (bids 32-95) + zero e (96-127)
        if (bid < 32) {
            int m0 = bid * 64;
            float acc[2][4] = {};
            mma_job(dyn, su, g_Wt1q + (size_t)m0 * NU, NU, g_s_h, g_s_l, NU, 16, acc);
            EPI_LOOP({
                int m = m0 + ml;
                if (m < NU) {
                    float tv = lut_eval(ltanh, v + by1[m]);
                    hilo16(tv, g_t1_h + nl * NU + m, g_t1_l + nl * NU + m);
                } else {
                    g_q[nl * NU + (m - NU)] = v + be1[m - NU];
                }
            });
        } else if (bid < 96) {
            int m0 = (bid - 32) * 64;
            float acc[2][4] = {};
            mma_job(dyn, su, g_Wgt + (size_t)m0 * 1536 + 512, 1536, g_s_h, g_s_l, NU, 16, acc);
            EPI_LOOP({
                g_gt[nl * 4096 + m0 + ml] = v;
            });
        } else if (bid < 128) {
            g_e[(bid - 96) * NTH + tid] = 0.f;
        }
        gsync(tgt);

        // P2: y split-K (bids 0-15) + energy partial dots (bids 16-143)
        if (bid < 16) {
            int m0 = (bid >> 1) * 64, kh = bid & 1;
            float acc[2][4] = {};
            mma_job(dyn, su, g_Wy2t + (size_t)m0 * NU + kh * 512, NU,
                    g_t1_h + kh * 512, g_t1_l + kh * 512, NU, 8, acc);
            EPI_LOOP({
                atomicAdd(&g_y32[nl * NT + m0 + ml], v);
            });
        } else if (bid < 144) {
            int e = bid - 16, b = e >> 1, uh = e & 1;
            float2* swq = (float2*)work;
            {
                int u = uh * 512 + tid;
                swq[tid] = make_float2(__ldcg(g_q + b * NU + u), We2[u]);
            }
            __syncthreads();
            int s = tid & 255, up = tid >> 8;
            const unsigned short* hp = (const unsigned short*)g_hpt +
                                       (size_t)(uh * 512 + up * 256) * NBS + b * NS + s;
            float av = 0.f;
#pragma unroll 8
            for (int u = 0; u < 256; u++) {
                unsigned short raw = __ldcg(hp + (size_t)u * NBS);
                float hv = __half2float(*reinterpret_cast<const __half*>(&raw));
                float2 qw = swq[up * 256 + u];
                av = fmaf(lut_eval(lsig, hv + qw.x), qw.y, av);
            }
            float* ew = work + 1024;
            ew[tid] = av;
            __syncthreads();
            if (tid < 256) atomicAdd(&g_e[b * NS + tid], ew[tid] + ew[tid + 256]);
        }
        gsync(tgt);

        // P4: gates-y (bids 0-63, K=512, fp32 B) + context w/ local softmax (64-127)
        if (bid < 64) {
            int m0 = bid * 64;
            float acc[2][4] = {};
            mma_job_f32b(dyn, su, g_Wgt + (size_t)m0 * 1536, 1536, g_y32, NT, 8, acc);
            EPI_LOOP({
                int gi = nl * 4096 + m0 + ml;
                g_gt[gi] = v + __ldcg(g_gt + gi);
            });
        } else if (bid < 128) {
            int b = bid - 64;
            float ev = (tid < NS) ? lut_eval(lsig, __ldcg(g_e + b * NS + tid) + be2v) : -1e30f;
            work[tid] = ev;
            __syncthreads();
            for (int o = 256; o > 0; o >>= 1) {
                if (tid < o) work[tid] = fmaxf(work[tid], work[tid + o]);
                __syncthreads();
            }
            float mx = work[0];
            __syncthreads();
            float p = expf(ev - mx);
            work[tid] = p;
            __syncthreads();
            for (int o = 256; o > 0; o >>= 1) {
                if (tid < o) work[tid] += work[tid + o];
                __syncthreads();
            }
            float rinv = 1.0f / work[0];
            float* aw = work + 512;
            if (tid < NS) aw[tid] = p * rinv;
            __syncthreads();
            const unsigned* hb = (const unsigned*)(g_h_h + (size_t)b * NS * NU) + tid;
            float a0 = 0.f, a1 = 0.f, a2 = 0.f, a3 = 0.f;
#pragma unroll 4
            for (int s2 = 0; s2 < NS; s2 += 2) {
                unsigned r0 = __ldcg(hb + (size_t)(s2 + 0) * (NU / 2));
                unsigned r1 = __ldcg(hb + (size_t)(s2 + 1) * (NU / 2));
                float2 f0 = __half22float2(*reinterpret_cast<const __half2*>(&r0));
                float2 f1 = __half22float2(*reinterpret_cast<const __half2*>(&r1));
                float w0 = aw[s2], w1 = aw[s2 + 1];
                a0 = fmaf(f0.x, w0, a0);
                a1 = fmaf(f0.y, w0, a1);
                a2 = fmaf(f1.x, w1, a2);
                a3 = fmaf(f1.y, w1, a3);
            }
            g_c_store:
            *(float2*)(work + 1536) = make_float2(0.f, 0.f);  // (unused; keep layout)
            g_q[0] += 0.f;                                     // no-op guard
            // store context directly to g_gt-adjacent scratch: reuse g_y32? No — keep g_c:
            // (we keep a dedicated buffer below)
            ((float*)g_e)[0] += 0.f;                           // no-op
            // write context
            extern __device__ float g_c[];
            g_c[b * NU + 2 * tid]     = a0 + a2;
            g_c[b * NU + 2 * tid + 1] = a1 + a3;
        }
        gsync(tgt);

        // P5: write y to out + reseed g_y32; s' = o * tanh(f*c + i*g)
        for (int i = gid; i < NB * NT; i += gth) {
            int n = i >> 9, m = i & 511;
            out[((size_t)n * NS + t) * NT + m] = __ldcg(g_y32 + i);
            g_y32[i] = by2[m];
        }
        for (int i = gid; i < NB * NU; i += gth) {
            int b = i >> 10, u = i & 1023;
            const float* gp = g_gt + b * 4096 + u;
            extern __device__ float g_c[];
            float iv = lut_eval(lsig,  __ldcg(gp)        + bi[u]);
            float fv = lut_eval(lsig,  __ldcg(gp + 1024) + bf[u]);
            float gv = lut_eval(ltanh, __ldcg(gp + 2048) + bg[u]);
            float ov = lut_eval(lsig,  __ldcg(gp + 3072) + bo[u]);
            float cv = __ldcg(g_c + i);
            float sv = ov * lut_eval(ltanh, fmaf(fv, cv, iv * gv));
            hilo16(sv, g_s_h + i, g_s_l + i);
        }
        gsync(tgt);
    }
}

__device__ float g_c[NB * NU];

extern "C" void kernel_launch(void* const* d_in, const int* in_sizes, int n_in,
                              void* d_out, int out_size) {
    (void)in_sizes; (void)n_in; (void)out_size;
    const float* h   = (const float*)d_in[0];
    const float* s0  = (const float*)d_in[1];
    const float* Wy1 = (const float*)d_in[2];
    const float* by1 = (const float*)d_in[3];
    const float* Wy2 = (const float*)d_in[4];
    const float* by2 = (const float*)d_in[5];
    const float* We1 = (const float*)d_in[6];
    const float* be1 = (const float*)d_in[7];
    const float* We2 = (const float*)d_in[8];
    const float* be2 = (const float*)d_in[9];
    const float* Wf  = (const float*)d_in[10];
    const float* bf  = (const float*)d_in[11];
    const float* Wi  = (const float*)d_in[12];
    const float* bi  = (const float*)d_in[13];
    const float* Wg  = (const float*)d_in[14];
    const float* bg  = (const float*)d_in[15];
    const float* Wo  = (const float*)d_in[16];
    const float* bo  = (const float*)d_in[17];
    float* out = (float*)d_out;

    int nsm = 148;
    cudaDeviceGetAttribute(&nsm, cudaDevAttrMultiProcessorCount, 0);
    static int sset = 0;
    if (!sset) {
        cudaFuncSetAttribute(k_all, cudaFuncAttributeMaxDynamicSharedMemorySize, PSMEM);
        sset = 1;
    }
    k_init<<<1, NTH>>>();
    k_all<<<nsm, NTH, PSMEM>>>(h, s0, Wy1, by1, Wy2, by2, We1, be1, We2, be2,
                               Wi, bi, Wf, bf, Wg, bg, Wo, bo, out);
}

// round 16
// speedup vs baseline: 1.3817x; 1.0506x over previous
#include <cuda_runtime.h>
#include <cuda_fp16.h>
#include <math.h>
#include <stdint.h>

#define NB 64
#define NS 256
#define NU 1024
#define NT 512
#define NTH 512
#define NBS (NB * NS)

__device__ __half g_h_h[NBS * NU], g_h_l[NBS * NU];   // fp16 hi/lo of h (lo: A2 only)
__device__ __half g_hpt[NBS * NU];                    // hproj^T [u][b*256+s]
__device__ __half g_Wt1q[2048 * NU];                  // fp16 weights (transposed)
__device__ __half g_Wy2t[NT * NU];
__device__ __half g_Wgt[4096 * 1536];
__device__ __half g_We1t[NU * NU];
__device__ __half g_t1[NB * NU];                      // single fp16 activations
__device__ __half g_s16[NB * NU];
__device__ float g_y32[NB * NT];
__device__ float g_q[NB * NU];
__device__ float g_c[NB * NU];
__device__ float g_e[NB * NS];
__device__ float g_gt[NB * 4096];
__device__ float2 g_lut_sig[2049], g_lut_tanh[2049];
__device__ unsigned g_cnt, g_phs;

#define O_LS 0
#define O_LT 16392
#define O_WK 32784
#define O_AH 44032
#define O_BH 52224
#define O_BL 60416
#define PSMEM 68608

#define SWZ(x) ((x) ^ (((x) >> 3) & 0x70))

__device__ __forceinline__ uint32_t smem_u32(const void* p) {
    uint32_t a;
    asm("{ .reg .u64 t; cvta.to.shared.u64 t, %1; cvt.u32.u64 %0, t; }" : "=r"(a) : "l"(p));
    return a;
}
__device__ __forceinline__ void ldsm4(uint32_t* r, uint32_t addr) {
    asm volatile("ldmatrix.sync.aligned.m8n8.x4.shared.b16 {%0,%1,%2,%3}, [%4];"
        : "=r"(r[0]), "=r"(r[1]), "=r"(r[2]), "=r"(r[3]) : "r"(addr));
}
__device__ __forceinline__ void hmma(float* d, const uint32_t* a, uint32_t b0, uint32_t b1) {
    asm volatile("mma.sync.aligned.m16n8k16.row.col.f32.f16.f16.f32 "
        "{%0,%1,%2,%3}, {%4,%5,%6,%7}, {%8,%9}, {%0,%1,%2,%3};"
        : "+f"(d[0]), "+f"(d[1]), "+f"(d[2]), "+f"(d[3])
        : "r"(a[0]), "r"(a[1]), "r"(a[2]), "r"(a[3]), "r"(b0), "r"(b1));
}
__device__ __forceinline__ float lut_eval(const float2* __restrict__ lut, float x) {
    float xc = fminf(fmaxf(x, -8.0f), 8.0f);
    float f  = fmaf(xc, 128.0f, 1024.0f);
    float m  = (f - 0.5f) + 12582912.0f;
    int  idx = __float_as_int(m) - 0x4B400000;
    float2 p = lut[idx];
    return fmaf(f - (m - 12582912.0f), p.y, p.x);
}
__device__ __forceinline__ void hilo16(float v, __half* hp, __half* lp) {
    __half h = __float2half_rn(v);
    *hp = h;
    *lp = __float2half_rn(v - __half2float(h));
}
__device__ __forceinline__ void gsync(unsigned& tgt) {
    tgt++;
    __syncthreads();
    if (threadIdx.x == 0) {
        __threadfence();
        if (atomicAdd(&g_cnt, 1u) == gridDim.x - 1) {
            g_cnt = 0; __threadfence(); atomicExch(&g_phs, tgt);
        } else {
            while (*(volatile unsigned*)&g_phs < tgt) { }
        }
    }
    __syncthreads();
}

__global__ void k_init() {
    int tid = threadIdx.x;
    if (tid == 0) { g_cnt = 0; g_phs = 0; }
    for (int i = tid; i < 2049; i += NTH) {
        float x0 = -8.0f + i * (1.0f / 128.0f), x1 = x0 + (1.0f / 128.0f);
        float sa = 1.0f / (1.0f + expf(-x0));
        float sb = (i == 2048) ? sa : 1.0f / (1.0f + expf(-x1));
        g_lut_sig[i] = make_float2(sa, sb - sa);
        float ta = tanhf(x0), tb = (i == 2048) ? ta : tanhf(x1);
        g_lut_tanh[i] = make_float2(ta, tb - ta);
    }
}

// ---- 1-term job: D = A(fp16) @ B(fp16)^T ; 8 HMMA/chunk ----
__device__ __forceinline__ void mma_job1(
    char* dyn, uint32_t su,
    const __half* A, int lda, const __half* B, int ldb,
    int nch, float acc[2][4])
{
    const int tid = threadIdx.x, lane = tid & 31, warp = tid >> 5;
    const int wm = warp >> 2, wn = warp & 3;
    const int sr = tid >> 3, ss = tid & 7;
    const int arow = wm * 16 + (lane & 15), ablk = lane >> 4;
    const int brow = wn * 16 + (lane & 7) + ((lane >> 4) << 3), bblk = (lane >> 3) & 1;
    const uint32_t soff = SWZ((uint32_t)(sr * 128 + ss * 16));

    uint4 va = *(const uint4*)(A + (size_t)sr * lda + ss * 8);
    uint4 vb = __ldcg((const uint4*)(B + (size_t)sr * ldb + ss * 8));
    for (int c = 0; c < nch; c++) {
        __syncthreads();
        *(uint4*)(dyn + O_AH + soff) = va;
        *(uint4*)(dyn + O_BH + soff) = vb;
        __syncthreads();
        if (c + 1 < nch) {
            int k = (c + 1) * 64 + ss * 8;
            va = *(const uint4*)(A + (size_t)sr * lda + k);
            vb = __ldcg((const uint4*)(B + (size_t)sr * ldb + k));
        }
#pragma unroll
        for (int ks = 0; ks < 4; ks++) {
            uint32_t ao = SWZ((uint32_t)(arow * 128 + ks * 32 + ablk * 16));
            uint32_t bo = SWZ((uint32_t)(brow * 128 + ks * 32 + bblk * 16));
            uint32_t ah[4], bh[4];
            ldsm4(ah, su + O_AH + ao);
            ldsm4(bh, su + O_BH + bo);
            hmma(acc[0], ah, bh[0], bh[1]);
            hmma(acc[1], ah, bh[2], bh[3]);
        }
    }
}

// ---- 2-term job (A2 only): B = fp16 hi/lo ----
__device__ __forceinline__ void mma_job2(
    char* dyn, uint32_t su,
    const __half* A, int lda,
    const __half* bH, const __half* bL, int ldb,
    int nch, float acc[2][4])
{
    const int tid = threadIdx.x, lane = tid & 31, warp = tid >> 5;
    const int wm = warp >> 2, wn = warp & 3;
    const int sr = tid >> 3, ss = tid & 7;
    const int arow = wm * 16 + (lane & 15), ablk = lane >> 4;
    const int brow = wn * 16 + (lane & 7) + ((lane >> 4) << 3), bblk = (lane >> 3) & 1;
    const uint32_t soff = SWZ((uint32_t)(sr * 128 + ss * 16));

    uint4 va  = *(const uint4*)(A + (size_t)sr * lda + ss * 8);
    uint4 vbh = __ldcg((const uint4*)(bH + (size_t)sr * ldb + ss * 8));
    uint4 vbl = __ldcg((const uint4*)(bL + (size_t)sr * ldb + ss * 8));
    for (int c = 0; c < nch; c++) {
        __syncthreads();
        *(uint4*)(dyn + O_AH + soff) = va;
        *(uint4*)(dyn + O_BH + soff) = vbh;
        *(uint4*)(dyn + O_BL + soff) = vbl;
        __syncthreads();
        if (c + 1 < nch) {
            int k = (c + 1) * 64 + ss * 8;
            va  = *(const uint4*)(A + (size_t)sr * lda + k);
            vbh = __ldcg((const uint4*)(bH + (size_t)sr * ldb + k));
            vbl = __ldcg((const uint4*)(bL + (size_t)sr * ldb + k));
        }
#pragma unroll
        for (int ks = 0; ks < 4; ks++) {
            uint32_t ao = SWZ((uint32_t)(arow * 128 + ks * 32 + ablk * 16));
            uint32_t bo = SWZ((uint32_t)(brow * 128 + ks * 32 + bblk * 16));
            uint32_t ah[4], bh[4], bl[4];
            ldsm4(ah, su + O_AH + ao);
            ldsm4(bh, su + O_BH + bo);
            ldsm4(bl, su + O_BL + bo);
            hmma(acc[0], ah, bh[0], bh[1]);
            hmma(acc[1], ah, bh[2], bh[3]);
            hmma(acc[0], ah, bl[0], bl[1]);
            hmma(acc[1], ah, bl[2], bl[3]);
        }
    }
}

// ---- 1-term job, B from fp32 (rounded to fp16 on the fly) ----
__device__ __forceinline__ void mma_job_f32b(
    char* dyn, uint32_t su,
    const __half* A, int lda,
    const float* bF, int ldb, int nch, float acc[2][4])
{
    const int tid = threadIdx.x, lane = tid & 31, warp = tid >> 5;
    const int wm = warp >> 2, wn = warp & 3;
    const int sr = tid >> 3, ss = tid & 7;
    const int arow = wm * 16 + (lane & 15), ablk = lane >> 4;
    const int brow = wn * 16 + (lane & 7) + ((lane >> 4) << 3), bblk = (lane >> 3) & 1;
    const uint32_t soff = SWZ((uint32_t)(sr * 128 + ss * 16));

    uint4 va = *(const uint4*)(A + (size_t)sr * lda + ss * 8);
    float fb[8];
    {
        float4 f0 = __ldcg((const float4*)(bF + (size_t)sr * ldb + ss * 8));
        float4 f1 = __ldcg((const float4*)(bF + (size_t)sr * ldb + ss * 8 + 4));
        fb[0] = f0.x; fb[1] = f0.y; fb[2] = f0.z; fb[3] = f0.w;
        fb[4] = f1.x; fb[5] = f1.y; fb[6] = f1.z; fb[7] = f1.w;
    }
    for (int c = 0; c < nch; c++) {
        uint16_t rh[8];
#pragma unroll
        for (int j = 0; j < 8; j++) {
            __half hh = __float2half_rn(fb[j]);
            rh[j] = *(uint16_t*)&hh;
        }
        uint4 vb = *(uint4*)rh;
        __syncthreads();
        *(uint4*)(dyn + O_AH + soff) = va;
        *(uint4*)(dyn + O_BH + soff) = vb;
        __syncthreads();
        if (c + 1 < nch) {
            int k = (c + 1) * 64 + ss * 8;
            va = *(const uint4*)(A + (size_t)sr * lda + k);
            float4 f0 = __ldcg((const float4*)(bF + (size_t)sr * ldb + k));
            float4 f1 = __ldcg((const float4*)(bF + (size_t)sr * ldb + k + 4));
            fb[0] = f0.x; fb[1] = f0.y; fb[2] = f0.z; fb[3] = f0.w;
            fb[4] = f1.x; fb[5] = f1.y; fb[6] = f1.z; fb[7] = f1.w;
        }
#pragma unroll
        for (int ks = 0; ks < 4; ks++) {
            uint32_t ao = SWZ((uint32_t)(arow * 128 + ks * 32 + ablk * 16));
            uint32_t bo = SWZ((uint32_t)(brow * 128 + ks * 32 + bblk * 16));
            uint32_t ah[4], bh[4];
            ldsm4(ah, su + O_AH + ao);
            ldsm4(bh, su + O_BH + bo);
            hmma(acc[0], ah, bh[0], bh[1]);
            hmma(acc[1], ah, bh[2], bh[3]);
        }
    }
}
#define EPI_LOOP(body) do {                                                     \
    const int _wm = (threadIdx.x >> 7), _wn = (threadIdx.x >> 5) & 3;           \
    const int _tq = (threadIdx.x & 31) >> 2, _tr = threadIdx.x & 3;             \
    _Pragma("unroll") for (int _i = 0; _i < 2; _i++) {                          \
        int ml = _wm * 16 + _tq + _i * 8;                                       \
        _Pragma("unroll") for (int _na = 0; _na < 2; _na++)                     \
        _Pragma("unroll") for (int _j = 0; _j < 2; _j++) {                      \
            int nl = _wn * 16 + _na * 8 + _tr * 2 + _j;                         \
            float v = acc[_na][_i * 2 + _j];                                    \
            body                                                                 \
        }                                                                        \
    }                                                                            \
} while (0)

__global__ __launch_bounds__(NTH, 1) void k_all(
    const float* __restrict__ h,  const float* __restrict__ s0,
    const float* __restrict__ Wy1, const float* __restrict__ by1,
    const float* __restrict__ Wy2, const float* __restrict__ by2,
    const float* __restrict__ We1, const float* __restrict__ be1,
    const float* __restrict__ We2, const float* __restrict__ be2,
    const float* __restrict__ Wi,  const float* __restrict__ bi,
    const float* __restrict__ Wf,  const float* __restrict__ bf,
    const float* __restrict__ Wg,  const float* __restrict__ bg,
    const float* __restrict__ Wo,  const float* __restrict__ bo,
    float* __restrict__ out)
{
    extern __shared__ char dyn[];
    float2* lsig  = (float2*)(dyn + O_LS);
    float2* ltanh = (float2*)(dyn + O_LT);
    float*  work  = (float*)(dyn + O_WK);
    const uint32_t su = smem_u32(dyn);
    const int tid = threadIdx.x, bid = blockIdx.x;
    const int gth = gridDim.x * NTH, gid = bid * NTH + tid;
    unsigned tgt = 0;

    for (int i = tid; i < 2049; i += NTH) { lsig[i] = g_lut_sig[i]; ltanh[i] = g_lut_tanh[i]; }
    __syncthreads();
    const float be2v = be2[0];

    // ---- A1: conversions + weight transposes ----
    for (size_t i = gid; i < (size_t)NBS * NU; i += gth)
        hilo16(__ldcs(h + i), g_h_h + i, g_h_l + i);
    for (int i = gid; i < 2048 * NU; i += gth) {
        int k = i >> 11, m = i & 2047;
        float v = (m < NU) ? Wy1[(size_t)k * NU + m] : We1[(size_t)(NU + k) * NU + (m - NU)];
        g_Wt1q[(size_t)m * NU + k] = __float2half_rn(v);
    }
    for (int i = gid; i < NT * NU; i += gth) {
        int k = i >> 9, m = i & 511;
        g_Wy2t[(size_t)m * NU + k] = __float2half_rn(Wy2[(size_t)k * NT + m]);
    }
    for (int i = gid; i < 4096 * 1536; i += gth) {
        int k = i >> 12, m = i & 4095, gate = m >> 10, u = m & 1023;
        const float* W = (gate == 0) ? Wi : (gate == 1) ? Wf : (gate == 2) ? Wg : Wo;
        g_Wgt[(size_t)m * 1536 + k] = __float2half_rn(W[(size_t)k * NU + u]);
    }
    for (int i = gid; i < NU * NU; i += gth) {
        int k = i >> 10, m = i & 1023;
        g_We1t[(size_t)m * NU + k] = __float2half_rn(We1[(size_t)k * NU + m]);
    }
    for (int i = gid; i < NB * NU; i += gth)
        g_s16[i] = __float2half_rn(s0[i]);
    for (int i = gid; i < NB * NT; i += gth)
        g_y32[i] = by2[i & 511];
    for (int i = gid; i < NB * NS; i += gth)
        g_e[i] = 0.f;
    gsync(tgt);

    // ---- A2: hproj = We1h^T @ h^T (2-term B for accuracy), 4096 jobs ----
    for (int j = bid; j < 4096; j += gridDim.x) {
        int m0 = (j >> 8) * 64, n0 = (j & 255) * 64;
        float acc[2][4] = {};
        mma_job2(dyn, su, g_We1t + (size_t)m0 * NU, NU,
                 g_h_h + (size_t)n0 * NU, g_h_l + (size_t)n0 * NU, NU, 16, acc);
        EPI_LOOP({
            g_hpt[(size_t)(m0 + ml) * NBS + n0 + nl] = __float2half_rn(v);
        });
    }
    gsync(tgt);

    // =========================== scan (4 barriers/step) ===========================
    for (int t = 0; t < NS; t++) {
        // P1: t1q (bids 0-31) + gates-s partial (bids 32-95) + zero e (96-127)
        if (bid < 32) {
            int m0 = bid * 64;
            float acc[2][4] = {};
            mma_job1(dyn, su, g_Wt1q + (size_t)m0 * NU, NU, g_s16, NU, 16, acc);
            EPI_LOOP({
                int m = m0 + ml;
                if (m < NU) {
                    g_t1[nl * NU + m] = __float2half_rn(lut_eval(ltanh, v + by1[m]));
                } else {
                    g_q[nl * NU + (m - NU)] = v + be1[m - NU];
                }
            });
        } else if (bid < 96) {
            int m0 = (bid - 32) * 64;
            float acc[2][4] = {};
            mma_job1(dyn, su, g_Wgt + (size_t)m0 * 1536 + 512, 1536, g_s16, NU, 16, acc);
            EPI_LOOP({
                g_gt[nl * 4096 + m0 + ml] = v;
            });
        } else if (bid < 128) {
            g_e[(bid - 96) * NTH + tid] = 0.f;
        }
        gsync(tgt);

        // P2: y split-K (bids 0-15) + energy partial dots (bids 16-143)
        if (bid < 16) {
            int m0 = (bid >> 1) * 64, kh = bid & 1;
            float acc[2][4] = {};
            mma_job1(dyn, su, g_Wy2t + (size_t)m0 * NU + kh * 512, NU,
                     g_t1 + kh * 512, NU, 8, acc);
            EPI_LOOP({
                atomicAdd(&g_y32[nl * NT + m0 + ml], v);
            });
        } else if (bid < 144) {
            int e = bid - 16, b = e >> 1, uh = e & 1;
            float2* swq = (float2*)work;
            {
                int u = uh * 512 + tid;
                swq[tid] = make_float2(__ldcg(g_q + b * NU + u), We2[u]);
            }
            __syncthreads();
            int s = tid & 255, up = tid >> 8;
            const unsigned short* hp = (const unsigned short*)g_hpt +
                                       (size_t)(uh * 512 + up * 256) * NBS + b * NS + s;
            float av = 0.f;
#pragma unroll 8
            for (int u = 0; u < 256; u++) {
                unsigned short raw = __ldcg(hp + (size_t)u * NBS);
                float hv = __half2float(*reinterpret_cast<const __half*>(&raw));
                float2 qw = swq[up * 256 + u];
                av = fmaf(lut_eval(lsig, hv + qw.x), qw.y, av);
            }
            float* ew = work + 1024;
            ew[tid] = av;
            __syncthreads();
            if (tid < 256) atomicAdd(&g_e[b * NS + tid], ew[tid] + ew[tid + 256]);
        }
        gsync(tgt);

        // P4: gates-y (bids 0-63, K=512, fp32 B) + context w/ local softmax (64-127)
        if (bid < 64) {
            int m0 = bid * 64;
            float acc[2][4] = {};
            mma_job_f32b(dyn, su, g_Wgt + (size_t)m0 * 1536, 1536, g_y32, NT, 8, acc);
            EPI_LOOP({
                int gi = nl * 4096 + m0 + ml;
                g_gt[gi] = v + __ldcg(g_gt + gi);
            });
        } else if (bid < 128) {
            int b = bid - 64;
            float ev = (tid < NS) ? lut_eval(lsig, __ldcg(g_e + b * NS + tid) + be2v) : -1e30f;
            work[tid] = ev;
            __syncthreads();
            for (int o = 256; o > 0; o >>= 1) {
                if (tid < o) work[tid] = fmaxf(work[tid], work[tid + o]);
                __syncthreads();
            }
            float mx = work[0];
            __syncthreads();
            float p = expf(ev - mx);
            work[tid] = p;
            __syncthreads();
            for (int o = 256; o > 0; o >>= 1) {
                if (tid < o) work[tid] += work[tid + o];
                __syncthreads();
            }
            float rinv = 1.0f / work[0];
            float* aw = work + 512;
            if (tid < NS) aw[tid] = p * rinv;
            __syncthreads();
            const unsigned* hb = (const unsigned*)(g_h_h + (size_t)b * NS * NU) + tid;
            float a0 = 0.f, a1 = 0.f, a2 = 0.f, a3 = 0.f;
#pragma unroll 4
            for (int s2 = 0; s2 < NS; s2 += 2) {
                unsigned r0 = __ldcg(hb + (size_t)(s2 + 0) * (NU / 2));
                unsigned r1 = __ldcg(hb + (size_t)(s2 + 1) * (NU / 2));
                float2 f0 = __half22float2(*reinterpret_cast<const __half2*>(&r0));
                float2 f1 = __half22float2(*reinterpret_cast<const __half2*>(&r1));
                float w0 = aw[s2], w1 = aw[s2 + 1];
                a0 = fmaf(f0.x, w0, a0);
                a1 = fmaf(f0.y, w0, a1);
                a2 = fmaf(f1.x, w1, a2);
                a3 = fmaf(f1.y, w1, a3);
            }
            g_c[b * NU + 2 * tid]     = a0 + a2;
            g_c[b * NU + 2 * tid + 1] = a1 + a3;
        }
        gsync(tgt);

        // P5: write y to out + reseed g_y32; s' = o * tanh(f*c + i*g)
        for (int i = gid; i < NB * NT; i += gth) {
            int n = i >> 9, m = i & 511;
            out[((size_t)n * NS + t) * NT + m] = __ldcg(g_y32 + i);
            g_y32[i] = by2[m];
        }
        for (int i = gid; i < NB * NU; i += gth) {
            int b = i >> 10, u = i & 1023;
            const float* gp = g_gt + b * 4096 + u;
            float iv = lut_eval(lsig,  __ldcg(gp)        + bi[u]);
            float fv = lut_eval(lsig,  __ldcg(gp + 1024) + bf[u]);
            float gv = lut_eval(ltanh, __ldcg(gp + 2048) + bg[u]);
            float ov = lut_eval(lsig,  __ldcg(gp + 3072) + bo[u]);
            float cv = __ldcg(g_c + i);
            float sv = ov * lut_eval(ltanh, fmaf(fv, cv, iv * gv));
            g_s16[i] = __float2half_rn(sv);
        }
        gsync(tgt);
    }
}

extern "C" void kernel_launch(void* const* d_in, const int* in_sizes, int n_in,
                              void* d_out, int out_size) {
    (void)in_sizes; (void)n_in; (void)out_size;
    const float* h   = (const float*)d_in[0];
    const float* s0  = (const float*)d_in[1];
    const float* Wy1 = (const float*)d_in[2];
    const float* by1 = (const float*)d_in[3];
    const float* Wy2 = (const float*)d_in[4];
    const float* by2 = (const float*)d_in[5];
    const float* We1 = (const float*)d_in[6];
    const float* be1 = (const float*)d_in[7];
    const float* We2 = (const float*)d_in[8];
    const float* be2 = (const float*)d_in[9];
    const float* Wf  = (const float*)d_in[10];
    const float* bf  = (const float*)d_in[11];
    const float* Wi  = (const float*)d_in[12];
    const float* bi  = (const float*)d_in[13];
    const float* Wg  = (const float*)d_in[14];
    const float* bg  = (const float*)d_in[15];
    const float* Wo  = (const float*)d_in[16];
    const float* bo  = (const float*)d_in[17];
    float* out = (float*)d_out;

    int nsm = 148;
    cudaDeviceGetAttribute(&nsm, cudaDevAttrMultiProcessorCount, 0);
    static int sset = 0;
    if (!sset) {
        cudaFuncSetAttribute(k_all, cudaFuncAttributeMaxDynamicSharedMemorySize, PSMEM);
        sset = 1;
    }
    k_init<<<1, NTH>>>();
    k_all<<<nsm, NTH, PSMEM>>>(h, s0, Wy1, by1, Wy2, by2, We1, be1, We2, be2,
                               Wi, bi, Wf, bf, Wg, bg, Wo, bo, out);
}